// round 17
// baseline (speedup 1.0000x reference)
#include <cuda_runtime.h>
#include <cuda_bf16.h>
#include <cstdint>

// ---------------------------------------------------------------------------
// Conv2d_STN: B=8, C=128, H=W=56, k=3, Ho=Wo=54, N=B*Ho*Wo=23328, O=256
// conv1: implicit-GEMM tf32 mma, 64-px blocks, m16xn64 warps, cp.async taps
// sample: bilinear gather + tf32 mma, 2-stage register pipeline.
// ---------------------------------------------------------------------------

#define Bsz   8
#define Cch   128
#define Hh    56
#define Ww    56
#define HW    3136
#define Ho    54
#define NHW   2916
#define Ntot  23328
#define Npix  25088         // 8*56*56
#define Oo    256
#define Kdim  1152
#define KSTEPS 144          // 1152 / 8

#define SCORE_OFF 0
#define DIFF_OFF  5971968
#define OUT_OFF   6111936
#define AUXX_OFF  6251904
#define AUXY_OFF  6461856

#define CH_LD   132                  // tile row stride (floats); banks (4r+q) distinct
#define CH_SZ   (32 * CH_LD)         // sample tap tile (32 rows)
#define C1_SZ   (64 * CH_LD)         // conv1 tap tile (64 rows)
#define SMEM_S  (2 * CH_SZ * 4)      // k_sample dynamic smem (33792 B)
#define SMEM_C1 (2 * C1_SZ * 4)      // k_conv1m dynamic smem (67584 B)

__device__ float  g_xt[Bsz * Hh * Ww * Cch];        // x channels-last, tf32-rounded
__device__ float  g_ht[Npix * Cch];                 // conv1 out channels-last
__device__ float2 g_wpk[KSTEPS * 32 * 32];          // lin_w  packed B-frags (tf32)
__device__ float2 g_w0pk[KSTEPS * 16 * 32];         // stn0_w packed B-frags (tf32)

__device__ __forceinline__ float to_tf32(float v) {
    float r;
    asm("cvt.rna.tf32.f32 %0, %1;" : "=f"(r) : "f"(v));
    return r;
}

#define MMA(acc, a0, a1, a2, a3, b0, b1)                                       \
    asm volatile(                                                              \
        "mma.sync.aligned.m16n8k8.row.col.f32.tf32.tf32.f32 "                  \
        "{%0,%1,%2,%3}, {%4,%5,%6,%7}, {%8,%9}, {%0,%1,%2,%3};"                \
        : "+f"(acc[0]), "+f"(acc[1]), "+f"(acc[2]), "+f"(acc[3])               \
        : "r"(a0), "r"(a1), "r"(a2), "r"(a3), "r"(b0), "r"(b1))

// ---------------- K_xt: NCHW -> NHWC transpose of x (+ tf32 round) ---------
__global__ __launch_bounds__(256) void k_xt(const float* __restrict__ x) {
    __shared__ float s[Cch][Ww + 1];
    const int b = blockIdx.y, y = blockIdx.x;
    const int tid = threadIdx.x;
    for (int e = tid; e < Cch * Ww; e += 256) {
        int c = e / Ww, xc = e % Ww;
        s[c][xc] = x[((b * Cch + c) * Hh + y) * Ww + xc];
    }
    __syncthreads();
    for (int e = tid; e < Cch * Ww; e += 256) {
        int xc = e >> 7, c = e & 127;
        g_xt[((b * Hh + y) * Ww + xc) * Cch + c] = to_tf32(s[c][xc]);
    }
}

// ---------------- K_packw: weight -> mma B-fragment layout (tf32) ----------
__global__ void k_packw(const float* __restrict__ w, float2* __restrict__ dst,
                        int ntiles) {
    int idx = blockIdx.x * 256 + threadIdx.x;
    if (idx >= KSTEPS * ntiles * 32) return;
    int lane  = idx & 31;
    int ntile = (idx >> 5) % ntiles;
    int ks    = (idx >> 5) / ntiles;
    int q = lane & 3, n = ntile * 8 + (lane >> 2);
    int kp1 = ks * 8 + q, kp2 = kp1 + 4;
    float v1 = w[n * Kdim + (kp1 & 127) * 9 + (kp1 >> 7)];
    float v2 = w[n * Kdim + (kp2 & 127) * 9 + (kp2 >> 7)];
    dst[idx] = make_float2(to_tf32(v1), to_tf32(v2));
}

// ---------------- K1: conv1 implicit-GEMM, 64 px, cp.async taps ------------
__global__ __launch_bounds__(256, 3) void k_conv1m(const float* __restrict__ bias) {
    extern __shared__ float s_buf[];            // [2][64][CH_LD]
    __shared__ int s_b[64], s_y[64], s_x[64];

    const int tid  = threadIdx.x;
    const int lane = tid & 31;
    const int wrp  = tid >> 5;
    const int p0   = blockIdx.x * 64;

    if (tid < 64) {
        int p = p0 + tid;
        int b = p / HW, rr = p % HW;
        s_b[tid] = b; s_y[tid] = rr / Ww; s_x[tid] = rr % Ww;
    }
    __syncthreads();

    const int mrow = (wrp & 3) * 16;      // 4 m-slabs over 64 px
    const int nt0  = (wrp >> 2) * 8;      // 2 n-groups x 8 tiles = 16 (N=128)
    const int r    = lane >> 2;
    const int q    = lane & 3;

    float acc[8][4];
    #pragma unroll
    for (int i = 0; i < 8; i++)
        #pragma unroll
        for (int j = 0; j < 4; j++) acc[i][j] = 0.f;

    // cp.async one tap tile: warp -> 8 pixels, lane -> 4 channels (16B)
    auto issue_tap = [&](int t, float* buf) {
        const int kh = t / 3, kw = t % 3;
        #pragma unroll
        for (int i = 0; i < 8; i++) {
            const int nn = wrp * 8 + i;
            const int yy = s_y[nn] + kh - 1;
            const int xx = s_x[nn] + kw - 1;
            const bool ok = ((unsigned)yy < 56u) && ((unsigned)xx < 56u);
            const int yc = min(max(yy, 0), 55), xc = min(max(xx, 0), 55);
            const float* src =
                &g_xt[(((s_b[nn] * Hh) + yc) * Ww + xc) * Cch + lane * 4];
            uint32_t dst = (uint32_t)__cvta_generic_to_shared(
                &buf[nn * CH_LD + lane * 4]);
            int sz = ok ? 16 : 0;
            asm volatile("cp.async.ca.shared.global [%0], [%1], 16, %2;"
                         :: "r"(dst), "l"(src), "r"(sz));
        }
        asm volatile("cp.async.commit_group;");
    };

    issue_tap(0, s_buf);

    for (int t = 0; t < 9; t++) {
        if (t < 8) {
            issue_tap(t + 1, s_buf + ((t + 1) & 1) * C1_SZ);
            asm volatile("cp.async.wait_group 1;");
        } else {
            asm volatile("cp.async.wait_group 0;");
        }
        __syncthreads();                    // tap t visible to all warps

        const float* cur = s_buf + (t & 1) * C1_SZ;
        const float* pa  = cur + (mrow + r) * CH_LD + q;
        const float* pa8 = pa + 8 * CH_LD;
        #pragma unroll 4
        for (int ksl = 0; ksl < 16; ksl++) {
            uint32_t a0 = __float_as_uint(pa [ksl * 8]);
            uint32_t a1 = __float_as_uint(pa8[ksl * 8]);
            uint32_t a2 = __float_as_uint(pa [ksl * 8 + 4]);
            uint32_t a3 = __float_as_uint(pa8[ksl * 8 + 4]);
            const float2* wp = g_w0pk + (((t * 16 + ksl) * 16) + nt0) * 32 + lane;
            #pragma unroll
            for (int i = 0; i < 8; i++) {
                float2 bv = wp[i * 32];
                MMA(acc[i], a0, a1, a2, a3,
                    __float_as_uint(bv.x), __float_as_uint(bv.y));
            }
        }
        __syncthreads();                    // buf[t&1] free for tap t+2
    }

    #pragma unroll
    for (int i = 0; i < 8; i++) {
        int o0 = (nt0 + i) * 8 + q * 2;
        float b0 = __ldg(&bias[o0]);
        float b1 = __ldg(&bias[o0 + 1]);
        int pA = p0 + mrow + r, pB = pA + 8;
        float2 vA = make_float2(fmaxf(acc[i][0] + b0, 0.f), fmaxf(acc[i][1] + b1, 0.f));
        float2 vB = make_float2(fmaxf(acc[i][2] + b0, 0.f), fmaxf(acc[i][3] + b1, 0.f));
        *(float2*)&g_ht[pA * Cch + o0] = vA;
        *(float2*)&g_ht[pB * Cch + o0] = vB;
    }
}

// ---------------- K2: conv2 warp-per-pixel on channels-last h --------------
__global__ __launch_bounds__(256) void k_conv2(const float* __restrict__ w1,
                                               const int* __restrict__ check,
                                               float* __restrict__ out) {
    __shared__ float s_w[9 * 6 * 128];     // [t][ch][c]
    const int tid  = threadIdx.x;
    const int lane = tid & 31;
    const int wrp  = tid >> 5;

    for (int e = tid; e < 9 * 6 * 128; e += 256) {
        int c = e & 127, tc = e >> 7;
        int t = tc / 6, ch = tc % 6;
        s_w[e] = w1[ch * Kdim + c * 9 + t];
    }
    __syncthreads();

    const int n  = blockIdx.x * 8 + wrp;
    const int b  = n / NHW, r = n % NHW;
    const int wo = r / Ho, ho = r % Ho;

    float acc[6] = {0,0,0,0,0,0};
    const float* hb = g_ht + ((b * Hh + ho) * Ww + wo) * Cch + lane * 4;
    #pragma unroll
    for (int i = 0; i < 3; i++) {
        #pragma unroll
        for (int j = 0; j < 3; j++) {
            float4 hv = *(const float4*)&hb[(i * Ww + j) * Cch];
            const int t = i * 3 + j;
            #pragma unroll
            for (int ch = 0; ch < 6; ch++) {
                float4 wv = *(const float4*)&s_w[(t * 6 + ch) * 128 + lane * 4];
                acc[ch] += hv.x * wv.x + hv.y * wv.y + hv.z * wv.z + hv.w * wv.w;
            }
        }
    }
    #pragma unroll
    for (int ch = 0; ch < 6; ch++) {
        #pragma unroll
        for (int off = 16; off > 0; off >>= 1)
            acc[ch] += __shfl_xor_sync(0xFFFFFFFFu, acc[ch], off);
    }

    const float scale = 1.0f - (float)check[0];
    const float ident6[6] = {1.f, 0.f, 0.f, 0.f, 1.f, 0.f};
    float th[6];
    #pragma unroll
    for (int ch = 0; ch < 6; ch++) th[ch] = acc[ch] * scale + ident6[ch];

    if (lane < 6) {
        out[OUT_OFF  + ((b * 6 + lane) * Ho + ho) * Ho + wo] = th[lane];
        out[DIFF_OFF + n * 6 + lane] = -(acc[lane] * scale);
    }
    if (lane < 9) {
        int i = lane / 3, j = lane % 3;
        float bi = (2.f * (float)i + 1.f) / 3.f - 1.f;
        float bj = (2.f * (float)j + 1.f) / 3.f - 1.f;
        float gx = th[0] * bj + th[1] * bi + th[2];
        float gy = th[3] * bj + th[4] * bi + th[5];
        out[AUXX_OFF + n * 9 + lane] = (gx + 1.0f + (float)wo) * (2.0f / 55.0f) - 1.0f;
        out[AUXY_OFF + n * 9 + lane] = (gy + 1.0f + (float)ho) * (2.0f / 55.0f) - 1.0f;
    }
}

// ---------------- K3: bilinear gather + tf32 GEMM, tap-streamed ------------
__global__ __launch_bounds__(256, 3) void k_sample(const float* __restrict__ lin_b,
                                                   float* __restrict__ out) {
    extern __shared__ float s_buf[];            // [2][32][CH_LD]
    __shared__ int   s_xi[288], s_yi[288];
    __shared__ float s_wx[288], s_wy[288];
    __shared__ int   s_xtoff[32], s_obase[32];

    const int tid  = threadIdx.x;
    const int lane = tid & 31;
    const int wrp  = tid >> 5;
    const int n0   = blockIdx.x * 32;

    if (tid < 32) {
        int n = n0 + tid;
        int b = n / NHW, r = n % NHW, wo = r / Ho, ho = r % Ho;
        s_xtoff[tid] = b * (Hh * Ww * Cch);
        s_obase[tid] = b * (Oo * NHW) + ho * Ho + wo;
    }
    for (int e = tid; e < 288; e += 256) {
        int nn = e / 9, t = e % 9;
        int n = n0 + nn;
        float ax = out[AUXX_OFF + n * 9 + t];
        float ay = out[AUXY_OFF + n * 9 + t];
        float gx = (ax + 1.0f) * 28.0f - 0.5f;
        float gy = (ay + 1.0f) * 28.0f - 0.5f;
        float x0f = floorf(gx), y0f = floorf(gy);
        s_xi[e] = (int)x0f;  s_yi[e] = (int)y0f;
        s_wx[e] = gx - x0f;  s_wy[e] = gy - y0f;
    }
    __syncthreads();

    const int mrow = (wrp & 1) * 16;
    const int nt0  = (wrp >> 1) * 8;
    const int r    = lane >> 2;
    const int q    = lane & 3;

    float acc[8][4];
    #pragma unroll
    for (int i = 0; i < 8; i++)
        #pragma unroll
        for (int j = 0; j < 4; j++) acc[i][j] = 0.f;

    auto gather = [&](int t, float* buf) {
        #pragma unroll
        for (int i = 0; i < 4; i++) {
            const int nn = wrp * 4 + i;
            const int task = nn * 9 + t;
            const int x0 = s_xi[task], y0 = s_yi[task];
            const float wx = s_wx[task], wy = s_wy[task];
            const float w00 = (1.f - wx) * (1.f - wy);
            const float w01 = wx * (1.f - wy);
            const float w10 = (1.f - wx) * wy;
            const float w11 = wx * wy;
            const bool vx0 = (unsigned)x0 < 56u, vx1 = (unsigned)(x0 + 1) < 56u;
            const bool vy0 = (unsigned)y0 < 56u, vy1 = (unsigned)(y0 + 1) < 56u;
            const float* base = g_xt + s_xtoff[nn] + lane * 4;
            const float4 z = make_float4(0.f, 0.f, 0.f, 0.f);
            float4 v00 = (vy0 && vx0) ? *(const float4*)(base + (y0 * Ww + x0) * Cch) : z;
            float4 v01 = (vy0 && vx1) ? *(const float4*)(base + (y0 * Ww + x0 + 1) * Cch) : z;
            float4 v10 = (vy1 && vx0) ? *(const float4*)(base + ((y0 + 1) * Ww + x0) * Cch) : z;
            float4 v11 = (vy1 && vx1) ? *(const float4*)(base + ((y0 + 1) * Ww + x0 + 1) * Cch) : z;
            float4 v;
            v.x = to_tf32(v00.x * w00 + v01.x * w01 + v10.x * w10 + v11.x * w11);
            v.y = to_tf32(v00.y * w00 + v01.y * w01 + v10.y * w10 + v11.y * w11);
            v.z = to_tf32(v00.z * w00 + v01.z * w01 + v10.z * w10 + v11.z * w11);
            v.w = to_tf32(v00.w * w00 + v01.w * w01 + v10.w * w10 + v11.w * w11);
            *(float4*)&buf[nn * CH_LD + lane * 4] = v;
        }
    };

    gather(0, s_buf);
    __syncthreads();

    for (int t = 0; t < 9; t++) {
        float* cur = s_buf + (t & 1) * CH_SZ;
        if (t < 8) gather(t + 1, s_buf + ((t + 1) & 1) * CH_SZ);

        const float* pa  = cur + (mrow + r) * CH_LD + q;
        const float* pa8 = pa + 8 * CH_LD;
        #pragma unroll 4
        for (int ksl = 0; ksl < 16; ksl++) {
            uint32_t a0 = __float_as_uint(pa [ksl * 8]);
            uint32_t a1 = __float_as_uint(pa8[ksl * 8]);
            uint32_t a2 = __float_as_uint(pa [ksl * 8 + 4]);
            uint32_t a3 = __float_as_uint(pa8[ksl * 8 + 4]);
            const float2* wp = g_wpk + (((t * 16 + ksl) * 32) + nt0) * 32 + lane;
            #pragma unroll
            for (int i = 0; i < 8; i++) {
                float2 bv = wp[i * 32];
                MMA(acc[i], a0, a1, a2, a3,
                    __float_as_uint(bv.x), __float_as_uint(bv.y));
            }
        }
        __syncthreads();
    }

    #pragma unroll
    for (int i = 0; i < 8; i++) {
        int o0 = (nt0 + i) * 8 + q * 2;
        float b0 = __ldg(&lin_b[o0]);
        float b1 = __ldg(&lin_b[o0 + 1]);
        int nnA = mrow + r, nnB = nnA + 8;
        out[SCORE_OFF + s_obase[nnA] + o0 * NHW]       = acc[i][0] + b0;
        out[SCORE_OFF + s_obase[nnA] + (o0 + 1) * NHW] = acc[i][1] + b1;
        out[SCORE_OFF + s_obase[nnB] + o0 * NHW]       = acc[i][2] + b0;
        out[SCORE_OFF + s_obase[nnB] + (o0 + 1) * NHW] = acc[i][3] + b1;
    }
}

// ---------------------------------------------------------------------------
extern "C" void kernel_launch(void* const* d_in, const int* in_sizes, int n_in,
                              void* d_out, int out_size) {
    const float* x      = (const float*)d_in[0];
    const float* stn0_w = (const float*)d_in[1];
    const float* stn0_b = (const float*)d_in[2];
    const float* stn1_w = (const float*)d_in[3];
    const float* lin_w  = (const float*)d_in[4];
    const float* lin_b  = (const float*)d_in[5];
    const int*   check  = (const int*)d_in[6];
    float* out = (float*)d_out;

    cudaFuncSetAttribute(k_conv1m, cudaFuncAttributeMaxDynamicSharedMemorySize,
                         SMEM_C1);

    float2* wpk;  cudaGetSymbolAddress((void**)&wpk,  g_wpk);
    float2* w0pk; cudaGetSymbolAddress((void**)&w0pk, g_w0pk);

    dim3 gxt(Hh, Bsz);
    k_xt<<<gxt, 256>>>(x);

    k_packw<<<(KSTEPS * 32 * 32 + 255) / 256, 256>>>(lin_w, wpk, 32);
    k_packw<<<(KSTEPS * 16 * 32 + 255) / 256, 256>>>(stn0_w, w0pk, 16);

    k_conv1m<<<Npix / 64, 256, SMEM_C1>>>(stn0_b);

    k_conv2<<<Ntot / 8, 256>>>(stn1_w, check, out);

    k_sample<<<Ntot / 32, 256, SMEM_S>>>(lin_b, out);
}